// round 14
// baseline (speedup 1.0000x reference)
#include <cuda_runtime.h>
#include <stdint.h>

#define BB 128
#define TT 1024
#define DD 256
#define UU 48
#define NCH 8      // logits chunks per batch (GR rows each)

// Scratch (allocation-free rule: __device__ globals)
__device__ float         g_logits[(size_t)BB * TT * UU];     // 25.2 MB
__device__ unsigned char g_bp[(size_t)(TT - 1) * BB * UU];   // 6.29 MB
__device__ int           g_last[BB];
__device__ int           g_done[BB * NCH];                   // per-(batch,chunk) flags

#define ADD_F32X2(out, a, b) \
    asm("add.rn.f32x2 %0, %1, %2;" : "=l"(out) : "l"(a), "l"(b))

__device__ __forceinline__ int ld_acquire_gpu(const int* p) {
    int v;
    asm volatile("ld.acquire.gpu.global.b32 %0, [%1];" : "=r"(v) : "l"(p) : "memory");
    return v;
}

#define GR 128     // gemm rows per block (one chunk of one batch)
#define GK 64
#define XPAD 130
#define NBF 128    // fwd blocks
#define NBG (BB * NCH)  // 1024 gemm blocks (chunk-major)

// ---------------------------------------------------------------------------
// Kernel 0: reset progress flags (must run before fused kernel each replay).
// ---------------------------------------------------------------------------
__global__ void reset_kernel() {
    int i = blockIdx.x * blockDim.x + threadIdx.x;
    if (i < BB * NCH) g_done[i] = 0;
}

// ---------------------------------------------------------------------------
// fwd step bodies (identical math to the R10/373us passing kernel).
// ---------------------------------------------------------------------------
__device__ __forceinline__ void value_step(const unsigned long long (&trv)[24],
                                           const float* __restrict__ stp,
                                           float* __restrict__ stn,
                                           int lu, bool act, float cur) {
    float v[24];
#pragma unroll
    for (int m = 0; m < 12; m++) {
        ulonglong2 s = *(const ulonglong2*)&stp[4 * m];
        unsigned long long ca, cb;
        ADD_F32X2(ca, s.x, trv[2 * m + 0]);
        ADD_F32X2(cb, s.y, trv[2 * m + 1]);
        float a0 = __uint_as_float((unsigned)(ca & 0xFFFFFFFFull));
        float a1 = __uint_as_float((unsigned)(ca >> 32));
        float b0 = __uint_as_float((unsigned)(cb & 0xFFFFFFFFull));
        float b1 = __uint_as_float((unsigned)(cb >> 32));
        v[2 * m + 0] = fmaxf(a0, a1);
        v[2 * m + 1] = fmaxf(b0, b1);
    }
#pragma unroll
    for (int j = 0; j < 12; j++) v[j] = fmaxf(v[2 * j], v[2 * j + 1]);
#pragma unroll
    for (int j = 0; j < 6; j++)  v[j] = fmaxf(v[2 * j], v[2 * j + 1]);
#pragma unroll
    for (int j = 0; j < 3; j++)  v[j] = fmaxf(v[2 * j], v[2 * j + 1]);
    float bv = fmaxf(fmaxf(v[0], v[1]), v[2]);
    if (act) stn[lu] = cur + bv;
}

// argmax over 48 candidates, first-index tie-break (strict-greater
// replacement, slots ascend with candidate index) — matches jnp.argmax.
__device__ __forceinline__ void index_step(const unsigned long long (&trv)[24],
                                           const float* __restrict__ stp,
                                           bool act, unsigned char* dst) {
    float v[24];
    int   ix[24];
#pragma unroll
    for (int m = 0; m < 12; m++) {
        ulonglong2 s = *(const ulonglong2*)&stp[4 * m];
        unsigned long long ca, cb;
        ADD_F32X2(ca, s.x, trv[2 * m + 0]);
        ADD_F32X2(cb, s.y, trv[2 * m + 1]);
        float a0 = __uint_as_float((unsigned)(ca & 0xFFFFFFFFull));
        float a1 = __uint_as_float((unsigned)(ca >> 32));
        float b0 = __uint_as_float((unsigned)(cb & 0xFFFFFFFFull));
        float b1 = __uint_as_float((unsigned)(cb >> 32));
        v[2 * m + 0]  = fmaxf(a0, a1);
        ix[2 * m + 0] = (a1 > a0) ? (4 * m + 1) : (4 * m + 0);
        v[2 * m + 1]  = fmaxf(b0, b1);
        ix[2 * m + 1] = (b1 > b0) ? (4 * m + 3) : (4 * m + 2);
    }
#pragma unroll
    for (int j = 0; j < 12; j++) {
        bool g = v[2 * j + 1] > v[2 * j];
        v[j]  = fmaxf(v[2 * j], v[2 * j + 1]);
        ix[j] = g ? ix[2 * j + 1] : ix[2 * j];
    }
#pragma unroll
    for (int j = 0; j < 6; j++) {
        bool g = v[2 * j + 1] > v[2 * j];
        v[j]  = fmaxf(v[2 * j], v[2 * j + 1]);
        ix[j] = g ? ix[2 * j + 1] : ix[2 * j];
    }
#pragma unroll
    for (int j = 0; j < 3; j++) {
        bool g = v[2 * j + 1] > v[2 * j];
        v[j]  = fmaxf(v[2 * j], v[2 * j + 1]);
        ix[j] = g ? ix[2 * j + 1] : ix[2 * j];
    }
    float m01 = fmaxf(v[0], v[1]);
    int  i01  = (v[1] > v[0]) ? ix[1] : ix[0];
    int  bi   = (v[2] > m01) ? ix[2] : i01;
    if (act) *dst = (unsigned char)bi;
}

// ---------------------------------------------------------------------------
// Fused kernel: blocks 0..127 = Viterbi forward (consumer), blocks
// 128..1151 = gemm (producer, chunk-major so chunk 0 lands first).
// gemm publishes its OWN (batch,chunk) flag: syncthreads -> threadfence ->
// atomicExch(flag,1). fwd gates each prefetch on ld.acquire of that flag
// (order-independent across chunks; acquire orders the subsequent LDGs).
// ---------------------------------------------------------------------------
__global__ __launch_bounds__(160, 3) void fused_kernel(
        const float* __restrict__ x, const float* __restrict__ w,
        const float* __restrict__ bias, const float* __restrict__ trans) {
    __shared__ __align__(16) float pool[GK * XPAD + GK * UU];  // 45568 B

    const int bid = blockIdx.x;
    const int tid = threadIdx.x;

    if (bid >= NBF) {
        // ================= GEMM role =================
        const int rb = bid - NBF;
        const int c  = rb >> 7;          // chunk 0..7 (chunk-major)
        const int bb = rb & 127;         // batch
        const size_t row0 = (size_t)bb * TT + (size_t)c * GR;

        float* xs = pool;                // [GK][XPAD]
        float* ws = pool + GK * XPAD;    // [GK][UU]

        const int tc = tid & 3;
        const int tr = tid >> 2;

        float acc[4][12];
#pragma unroll
        for (int i = 0; i < 4; i++)
#pragma unroll
            for (int j = 0; j < 12; j++) acc[i][j] = 0.0f;

        for (int kc = 0; kc < DD; kc += GK) {
            if (tid < 128) {
                const float4* wg = (const float4*)(w + (size_t)kc * UU);
                float4* wsv = (float4*)ws;
#pragma unroll
                for (int i = 0; i < 6; i++) wsv[tid + i * 128] = wg[tid + i * 128];
#pragma unroll
                for (int i = 0; i < 16; i++) {
                    int j  = tid + i * 128;
                    int r  = j >> 4;
                    int k4 = j & 15;
                    float4 f = *(const float4*)(x + (row0 + (size_t)r) * DD + kc + k4 * 4);
                    xs[(k4 * 4 + 0) * XPAD + r] = f.x;
                    xs[(k4 * 4 + 1) * XPAD + r] = f.y;
                    xs[(k4 * 4 + 2) * XPAD + r] = f.z;
                    xs[(k4 * 4 + 3) * XPAD + r] = f.w;
                }
            }
            __syncthreads();

            if (tid < 128) {
#pragma unroll 4
                for (int k = 0; k < GK; k++) {
                    float xv[4], wv[12];
                    float2 xa = *(const float2*)&xs[k * XPAD + tr * 4];
                    float2 xb = *(const float2*)&xs[k * XPAD + tr * 4 + 2];
                    xv[0] = xa.x; xv[1] = xa.y; xv[2] = xb.x; xv[3] = xb.y;
#pragma unroll
                    for (int q = 0; q < 3; q++) {
                        float4 wq = *(const float4*)&ws[k * UU + tc * 12 + q * 4];
                        wv[q * 4 + 0] = wq.x; wv[q * 4 + 1] = wq.y;
                        wv[q * 4 + 2] = wq.z; wv[q * 4 + 3] = wq.w;
                    }
#pragma unroll
                    for (int i = 0; i < 4; i++)
#pragma unroll
                        for (int j = 0; j < 12; j++) acc[i][j] += xv[i] * wv[j];
                }
            }
            __syncthreads();
        }

        if (tid < 128) {
            float bv[12];
#pragma unroll
            for (int j = 0; j < 12; j++) bv[j] = bias[tc * 12 + j];
#pragma unroll
            for (int i = 0; i < 4; i++) {
                size_t r = row0 + tr * 4 + i;
                float* o = g_logits + r * UU + tc * 12;
#pragma unroll
                for (int j = 0; j < 12; j++) o[j] = acc[i][j] + bv[j];
            }
        }
        __syncthreads();                    // block writes ordered before fence
        if (tid == 0) {
            __threadfence();                // publish block's STGs device-wide
            atomicExch(&g_done[bb * NCH + c], 1);
        }
        return;
    }

    // ================= FWD role (R10 body + per-chunk acquire gate) =========
    const int b = bid;
    float* st0 = pool;                      // st[2][UU] carved from pool

    // warp 4 (tid 128-159): idle, but must match every __syncthreads.
    if (tid >= 128) {
        __syncthreads();                    // pre-loop barrier
        for (int i = 0; i < TT - 1; i++) __syncthreads();
        return;
    }

    const bool is_val = (tid < 64);
    const int  lu     = is_val ? tid : (tid - 64);
    const bool act    = (lu < UU);
    const int  u      = act ? lu : (UU - 1);

    unsigned long long trv[24];
#pragma unroll
    for (int j = 0; j < 24; j++) {
        unsigned lo = __float_as_uint(trans[(2 * j) * UU + u]);
        unsigned hi = __float_as_uint(trans[(2 * j + 1) * UU + u]);
        trv[j] = (unsigned long long)lo | ((unsigned long long)hi << 32);
    }

    const float* lg = g_logits + (size_t)b * TT * UU + u;
    const int* flags = &g_done[b * NCH];
    int conf = -1;                          // highest chunk confirmed done

    float fb[4];
    if (is_val) {
        while (ld_acquire_gpu(&flags[0]) == 0) __nanosleep(200);
        conf = 0;
        if (act) st0[lu] = lg[0];
        fb[0] = lg[(size_t)1 * UU];
        fb[1] = lg[(size_t)2 * UU];
        fb[2] = lg[(size_t)3 * UU];
        fb[3] = lg[(size_t)4 * UU];
    }
    unsigned char* bpb = g_bp + (size_t)b * UU + u;

    __syncthreads();

    int p = 0;
    int tb = 1;
    for (; tb + 3 < TT; tb += 4) {
#pragma unroll
        for (int q = 0; q < 4; q++) {
            const int t = tb + q;
            if (is_val) {
                float cur = fb[q];
                int tn = t + 4;
                if (tn > TT - 1) tn = TT - 1;
                int need = tn >> 7;         // chunk of row tn (monotone in t)
                if (need > conf) {
                    while (ld_acquire_gpu(&flags[need]) == 0) __nanosleep(100);
                    conf = need;
                }
                fb[q] = lg[(size_t)tn * UU];
                value_step(trv, st0 + p * UU, st0 + (p ^ 1) * UU, lu, act, cur);
            } else {
                index_step(trv, st0 + p * UU, act,
                           bpb + (size_t)(t - 1) * BB * UU);
            }
            __syncthreads();
            p ^= 1;
        }
    }
#pragma unroll
    for (int q = 0; q < 3; q++) {
        const int t = tb + q;
        if (t < TT) {
            if (is_val) {
                value_step(trv, st0 + p * UU, st0 + (p ^ 1) * UU, lu, act, fb[q]);
            } else {
                index_step(trv, st0 + p * UU, act,
                           bpb + (size_t)(t - 1) * BB * UU);
            }
            __syncthreads();
            p ^= 1;
        }
    }

    if (tid == 0) {
        const float* stf = st0 + p * UU;
        float bv = stf[0];
        int bi = 0;
#pragma unroll
        for (int i = 1; i < UU; i++) {
            if (stf[i] > bv) { bv = stf[i]; bi = i; }
        }
        g_last[b] = bi;
    }
}

// ---------------------------------------------------------------------------
// Kernel 3: backtrack + emit (measured 29.5us). 128 blocks, 256 threads.
// ---------------------------------------------------------------------------
__global__ __launch_bounds__(256) void backtrack_kernel(float* __restrict__ out) {
    __shared__ unsigned char sbp[(TT - 1) * UU];  // 49104 B

    const int b = blockIdx.x;
    const int tid = threadIdx.x;

    const unsigned char* gsrc = g_bp + (size_t)b * UU;
    for (int idx = tid; idx < (TT - 1) * 3; idx += 256) {
        int s = idx / 3;
        int w = idx % 3;
        uint4 v = *(const uint4*)(gsrc + (size_t)s * BB * UU + w * 16);
        *(uint4*)(sbp + s * UU + w * 16) = v;
    }
    __syncthreads();

    if (tid != 0) return;

    int tag = g_last[b];
    float* ob = out + (size_t)b * TT;
    ob[TT - 1] = (float)tag;

    int off = (TT - 2) * UU;
#pragma unroll 8
    for (int s = TT - 2; s >= 0; --s) {
        tag = sbp[off + tag];
        ob[s] = (float)tag;
        off -= UU;
    }
}

// ---------------------------------------------------------------------------
extern "C" void kernel_launch(void* const* d_in, const int* in_sizes, int n_in,
                              void* d_out, int out_size) {
    const float* x     = (const float*)d_in[0];  // (128,1024,256)
    const float* kern  = (const float*)d_in[1];  // (256,48)
    const float* bias  = (const float*)d_in[2];  // (48,)
    const float* chain = (const float*)d_in[3];  // (48,48)
    float* out = (float*)d_out;                  // (128,1024) float32

    reset_kernel<<<1, 1024>>>();
    fused_kernel<<<NBF + NBG, 160>>>(x, kern, bias, chain);
    backtrack_kernel<<<BB, 256>>>(out);
}

// round 15
// speedup vs baseline: 1.3042x; 1.3042x over previous
#include <cuda_runtime.h>
#include <stdint.h>

#define BB 128
#define TT 1024
#define DD 256
#define UU 48

// Scratch (allocation-free rule: __device__ globals)
__device__ float         g_logits[(size_t)BB * TT * UU];     // 25.2 MB
__device__ unsigned char g_bp[(size_t)(TT - 1) * BB * UU];   // 6.29 MB
__device__ int           g_last[BB];

#define ADD_F32X2(out, a, b) \
    asm("add.rn.f32x2 %0, %1, %2;" : "=l"(out) : "l"(a), "l"(b))

// ---------------------------------------------------------------------------
// Kernel 1: logits = x @ kernel + bias (measured ~106us ~ 1.12x fp32 floor)
// ---------------------------------------------------------------------------
#define GR 128
#define GK 64
#define XPAD 130

__global__ __launch_bounds__(128) void gemm_kernel(const float* __restrict__ x,
                                                   const float* __restrict__ w,
                                                   const float* __restrict__ bias) {
    __shared__ float xs[GK][XPAD];
    __shared__ float ws[GK][UU];

    const int tid = threadIdx.x;
    const int tc  = tid & 3;
    const int tr  = tid >> 2;
    const size_t row0 = (size_t)blockIdx.x * GR;

    float acc[4][12];
#pragma unroll
    for (int i = 0; i < 4; i++)
#pragma unroll
        for (int j = 0; j < 12; j++) acc[i][j] = 0.0f;

    for (int kc = 0; kc < DD; kc += GK) {
        const float4* wg = (const float4*)(w + (size_t)kc * UU);
        float4* wsv = (float4*)&ws[0][0];
#pragma unroll
        for (int i = 0; i < 6; i++) wsv[tid + i * 128] = wg[tid + i * 128];

#pragma unroll
        for (int i = 0; i < 16; i++) {
            int j  = tid + i * 128;
            int r  = j >> 4;
            int k4 = j & 15;
            float4 f = *(const float4*)(x + (row0 + (size_t)r) * DD + kc + k4 * 4);
            xs[k4 * 4 + 0][r] = f.x;
            xs[k4 * 4 + 1][r] = f.y;
            xs[k4 * 4 + 2][r] = f.z;
            xs[k4 * 4 + 3][r] = f.w;
        }
        __syncthreads();

#pragma unroll 4
        for (int k = 0; k < GK; k++) {
            float xv[4], wv[12];
            float2 xa = *(const float2*)&xs[k][tr * 4];
            float2 xb = *(const float2*)&xs[k][tr * 4 + 2];
            xv[0] = xa.x; xv[1] = xa.y; xv[2] = xb.x; xv[3] = xb.y;
#pragma unroll
            for (int q = 0; q < 3; q++) {
                float4 wq = *(const float4*)&ws[k][tc * 12 + q * 4];
                wv[q * 4 + 0] = wq.x; wv[q * 4 + 1] = wq.y;
                wv[q * 4 + 2] = wq.z; wv[q * 4 + 3] = wq.w;
            }
#pragma unroll
            for (int i = 0; i < 4; i++)
#pragma unroll
                for (int j = 0; j < 12; j++) acc[i][j] += xv[i] * wv[j];
        }
        __syncthreads();
    }

    float bv[12];
#pragma unroll
    for (int j = 0; j < 12; j++) bv[j] = bias[tc * 12 + j];

#pragma unroll
    for (int i = 0; i < 4; i++) {
        size_t r = row0 + tr * 4 + i;
        float* o = g_logits + r * UU + tc * 12;
#pragma unroll
        for (int j = 0; j < 12; j++) o[j] = acc[i][j] + bv[j];
    }
}

// ---------------------------------------------------------------------------
// Unified (val, argmax-first-index) over 24 candidates [base, base+24).
// Strict-greater replacement, slots ascend with candidate index =>
// first-index tie-break (matches jnp.argmax). Value path = fmaxf.
// ---------------------------------------------------------------------------
__device__ __forceinline__ void valIdx24(const unsigned long long (&tr2)[12],
                                         const float* __restrict__ stp,
                                         int base, float& bvo, int& bio) {
    float v[12];
    int   ix[12];
#pragma unroll
    for (int m = 0; m < 6; m++) {
        ulonglong2 s = *(const ulonglong2*)&stp[base + 4 * m];
        unsigned long long ca, cb;
        ADD_F32X2(ca, s.x, tr2[2 * m + 0]);
        ADD_F32X2(cb, s.y, tr2[2 * m + 1]);
        float a0 = __uint_as_float((unsigned)(ca & 0xFFFFFFFFull));
        float a1 = __uint_as_float((unsigned)(ca >> 32));
        float b0 = __uint_as_float((unsigned)(cb & 0xFFFFFFFFull));
        float b1 = __uint_as_float((unsigned)(cb >> 32));
        v[2 * m + 0]  = fmaxf(a0, a1);
        ix[2 * m + 0] = (a1 > a0) ? (4 * m + 1) : (4 * m + 0);
        v[2 * m + 1]  = fmaxf(b0, b1);
        ix[2 * m + 1] = (b1 > b0) ? (4 * m + 3) : (4 * m + 2);
    }
#pragma unroll
    for (int j = 0; j < 6; j++) {
        bool g = v[2 * j + 1] > v[2 * j];
        v[j]  = fmaxf(v[2 * j], v[2 * j + 1]);
        ix[j] = g ? ix[2 * j + 1] : ix[2 * j];
    }
#pragma unroll
    for (int j = 0; j < 3; j++) {
        bool g = v[2 * j + 1] > v[2 * j];
        v[j]  = fmaxf(v[2 * j], v[2 * j + 1]);
        ix[j] = g ? ix[2 * j + 1] : ix[2 * j];
    }
    float m01 = fmaxf(v[0], v[1]);
    int  i01  = (v[1] > v[0]) ? ix[1] : ix[0];
    bvo = fmaxf(m01, v[2]);
    bio = ((v[2] > m01) ? ix[2] : i01) + base;
}

// ---------------------------------------------------------------------------
// Kernel 2: Viterbi forward, UNIFIED layout (min max-SMSP load):
// 96 threads / 3 warps (one per SMSP 0-2, SMSP3 idle). Each lane computes
// (val, idx) over 24 candidates for output u = tid>>1, half h = tid&1
// (~95 instrs -> ~190 cyc/SMSP vs 352 in the role-split R10 layout).
// Halves combine via shfl.down 1: value fmaxf; index strict-greater from
// the high half (low half = smaller indices wins ties). h==0 lane writes
// both st[p^1][u] and bp. t-loop unrolled x4 with statically-indexed
// prefetch regs (R10 fix: LDG consumed 4 steps after issue).
// ---------------------------------------------------------------------------
__global__ __launch_bounds__(96) void viterbi_fwd(const float* __restrict__ trans) {
    const int b    = blockIdx.x;
    const int tid  = threadIdx.x;
    const int u    = tid >> 1;
    const int h    = tid & 1;
    const int base = 24 * h;

    __shared__ __align__(16) float st[2][UU];

    unsigned long long tr2[12];
#pragma unroll
    for (int j = 0; j < 12; j++) {
        unsigned lo = __float_as_uint(trans[(base + 2 * j) * UU + u]);
        unsigned hi = __float_as_uint(trans[(base + 2 * j + 1) * UU + u]);
        tr2[j] = (unsigned long long)lo | ((unsigned long long)hi << 32);
    }

    const float* lg = g_logits + (size_t)b * TT * UU + u;
    if (h == 0) st[0][u] = lg[0];

    float fb[4];
    fb[0] = lg[(size_t)1 * UU];
    fb[1] = lg[(size_t)2 * UU];
    fb[2] = lg[(size_t)3 * UU];
    fb[3] = lg[(size_t)4 * UU];

    unsigned char* bpb = g_bp + (size_t)b * UU + u;

    __syncthreads();

    int p = 0;
    int tb = 1;
    for (; tb + 3 < TT; tb += 4) {
#pragma unroll
        for (int q = 0; q < 4; q++) {
            const int t = tb + q;
            float cur = fb[q];
            int tn = t + 4;
            if (tn > TT - 1) tn = TT - 1;
            fb[q] = lg[(size_t)tn * UU];        // consumed 4 steps later

            float bv; int bi;
            valIdx24(tr2, st[p], base, bv, bi);

            float ov = __shfl_down_sync(0xFFFFFFFFu, bv, 1);
            int   oi = __shfl_down_sync(0xFFFFFFFFu, bi, 1);
            float mv = fmaxf(bv, ov);           // value: FMNMX on chain
            int   mi = (ov > bv) ? oi : bi;     // index: high half strict >

            if (h == 0) {
                st[p ^ 1][u] = cur + mv;
                bpb[(size_t)(t - 1) * BB * UU] = (unsigned char)mi;
            }
            __syncthreads();
            p ^= 1;
        }
    }
    // epilogue: t = tb .. TT-1 (3 steps; fb[0..2] already hold their logits)
#pragma unroll
    for (int q = 0; q < 3; q++) {
        const int t = tb + q;
        if (t < TT) {
            float bv; int bi;
            valIdx24(tr2, st[p], base, bv, bi);
            float ov = __shfl_down_sync(0xFFFFFFFFu, bv, 1);
            int   oi = __shfl_down_sync(0xFFFFFFFFu, bi, 1);
            float mv = fmaxf(bv, ov);
            int   mi = (ov > bv) ? oi : bi;
            if (h == 0) {
                st[p ^ 1][u] = fb[q] + mv;
                bpb[(size_t)(t - 1) * BB * UU] = (unsigned char)mi;
            }
            __syncthreads();
            p ^= 1;
        }
    }

    if (tid == 0) {
        float bv = st[p][0];
        int bi = 0;
#pragma unroll
        for (int i = 1; i < UU; i++) {
            if (st[p][i] > bv) { bv = st[p][i]; bi = i; }
        }
        g_last[b] = bi;
    }
}

// ---------------------------------------------------------------------------
// Kernel 3: backtrack + emit (measured 29.5us). 128 blocks, 256 threads.
// Stage bp column to SMEM, branchless LDS.U8 chain walk, float output.
// ---------------------------------------------------------------------------
__global__ __launch_bounds__(256) void backtrack_kernel(float* __restrict__ out) {
    __shared__ unsigned char sbp[(TT - 1) * UU];  // 49104 B

    const int b = blockIdx.x;
    const int tid = threadIdx.x;

    const unsigned char* gsrc = g_bp + (size_t)b * UU;
    for (int idx = tid; idx < (TT - 1) * 3; idx += 256) {
        int s = idx / 3;
        int w = idx % 3;
        uint4 v = *(const uint4*)(gsrc + (size_t)s * BB * UU + w * 16);
        *(uint4*)(sbp + s * UU + w * 16) = v;
    }
    __syncthreads();

    if (tid != 0) return;

    int tag = g_last[b];
    float* ob = out + (size_t)b * TT;
    ob[TT - 1] = (float)tag;

    int off = (TT - 2) * UU;
#pragma unroll 8
    for (int s = TT - 2; s >= 0; --s) {
        tag = sbp[off + tag];
        ob[s] = (float)tag;
        off -= UU;
    }
}

// ---------------------------------------------------------------------------
extern "C" void kernel_launch(void* const* d_in, const int* in_sizes, int n_in,
                              void* d_out, int out_size) {
    const float* x     = (const float*)d_in[0];  // (128,1024,256)
    const float* kern  = (const float*)d_in[1];  // (256,48)
    const float* bias  = (const float*)d_in[2];  // (48,)
    const float* chain = (const float*)d_in[3];  // (48,48)
    float* out = (float*)d_out;                  // (128,1024) float32

    gemm_kernel<<<(BB * TT) / GR, 128>>>(x, kern, bias);
    viterbi_fwd<<<BB, 96>>>(chain);
    backtrack_kernel<<<BB, 256>>>(out);
}